// round 11
// baseline (speedup 1.0000x reference)
#include <cuda_runtime.h>

// x:    [B, C, H, W] float32   flow: [B, H, W, 2] float32   out: [B, C, H, W]
// Bilinear warp, align_corners=True; identity grid folds into pixel index.
//
// Gather strategy: j2 = j1+1, so both j-taps of a row live in one 16B-aligned
// float4 for 75% of lanes. One LDG.128 + register select replaces two scalar
// gathers; a predicated scalar LDG covers the j1%4==3 stragglers. This cuts
// L1 wavefronts on the dominant (i-scattered) gather stream ~30%.

#define B_   32
#define C_   3
#define H_   512
#define W_   512
#define LOGW 9
#define HW_  (H_ * W_)
#define TILE_W 64
#define TILE_H 8

__device__ __forceinline__ float sel4(const float4& v, unsigned r) {
    float t = (r == 0) ? v.x : (r == 1) ? v.y : (r == 2) ? v.z : v.w;
    return t;
}

struct Px {
    unsigned e1, e2;      // 16B-aligned element offsets for rows i1, i2
    unsigned r;           // j1 & 3
    bool     need_x;      // r==3 && j1 < W-1  (straggler load)
    bool     j_edge;      // j1 == W-1  (q12 = q11)
    float w11, w12, w21, w22;
};

__device__ __forceinline__ Px make_px(float fi, float fj) {
    const float Hm1 = (float)(H_ - 1), Wm1 = (float)(W_ - 1);
    const float i1f = fminf(fmaxf(floorf(fi), 0.0f), Hm1);
    const float j1f = fminf(fmaxf(floorf(fj), 0.0f), Wm1);
    const float i2f = fminf(i1f + 1.0f, Hm1);
    const float di = fi - i1f;
    const float dj = fj - j1f;

    const unsigned i1 = (unsigned)i1f, i2 = (unsigned)i2f, j1 = (unsigned)j1f;

    Px p;
    p.r      = j1 & 3u;
    p.need_x = (p.r == 3u) && (j1 < (unsigned)(W_ - 1));
    p.j_edge = (j1 == (unsigned)(W_ - 1));
    p.e1 = (i1 << LOGW) + (j1 & ~3u);
    p.e2 = (i2 << LOGW) + (j1 & ~3u);
    p.w11 = (1.0f - di) * (1.0f - dj);
    p.w21 = di * (1.0f - dj);
    p.w12 = (1.0f - di) * dj;
    p.w22 = di * dj;
    return p;
}

__device__ __forceinline__ float interp_c(const float* __restrict__ xc, const Px& p) {
    const float4 A = __ldg(reinterpret_cast<const float4*>(xc + p.e1));
    const float4 Bv = __ldg(reinterpret_cast<const float4*>(xc + p.e2));

    float xa = 0.0f, xb = 0.0f;
    if (p.need_x) {                       // predicated straggler loads
        xa = __ldg(xc + p.e1 + 4);
        xb = __ldg(xc + p.e2 + 4);
    }

    const float q11 = sel4(A, p.r);
    const float q21 = sel4(Bv, p.r);
    float q12, q22;
    if (p.r < 3u) {
        q12 = sel4(A, p.r + 1u);
        q22 = sel4(Bv, p.r + 1u);
    } else {
        q12 = p.j_edge ? q11 : xa;
        q22 = p.j_edge ? q21 : xb;
    }
    return q11 * p.w11 + q21 * p.w21 + q12 * p.w12 + q22 * p.w22;
}

__global__ __launch_bounds__(256)
void flow_warp_kernel(const float* __restrict__ x,
                      const float2* __restrict__ flow,
                      float* __restrict__ out)
{
    const unsigned tid  = threadIdx.x;
    const unsigned warp = tid >> 5;
    const unsigned lane = tid & 31u;

    const unsigned b  = blockIdx.z;
    const unsigned i  = blockIdx.y * TILE_H + warp;
    const unsigned j0 = blockIdx.x * TILE_W + lane;
    const unsigned j1 = j0 + 32;

    const unsigned hw0  = (i << LOGW) + j0;
    const unsigned hw1  = hw0 + 32;
    const unsigned bhw0 = (b << 18) + hw0;

    const float2 f0 = flow[bhw0];
    const float2 f1 = flow[bhw0 + 32];

    const float Hm1 = (float)(H_ - 1), Wm1 = (float)(W_ - 1);
    const float fi0 = (float)i  + Hm1 * 0.5f * f0.y;
    const float fj0 = (float)j0 + Wm1 * 0.5f * f0.x;
    const float fi1 = (float)i  + Hm1 * 0.5f * f1.y;
    const float fj1 = (float)j1 + Wm1 * 0.5f * f1.x;

    const Px p0 = make_px(fi0, fj0);
    const Px p1 = make_px(fi1, fj1);

    const unsigned base = b * (C_ * HW_);
    const float* xb = x + base;
    float* ob = out + base;

    #pragma unroll
    for (int c = 0; c < C_; ++c) {
        const float* xc = xb + c * HW_;
        ob[c * HW_ + hw0] = interp_c(xc, p0);
        ob[c * HW_ + hw1] = interp_c(xc, p1);
    }
}

extern "C" void kernel_launch(void* const* d_in, const int* in_sizes, int n_in,
                              void* d_out, int out_size)
{
    const float*  x    = (const float*)d_in[0];
    const float2* flow = (const float2*)d_in[1];
    float* out = (float*)d_out;

    dim3 grid(W_ / TILE_W, H_ / TILE_H, B_);   // (8, 64, 32)
    flow_warp_kernel<<<grid, 256>>>(x, flow, out);
}

// round 13
// speedup vs baseline: 1.5721x; 1.5721x over previous
#include <cuda_runtime.h>

// x:    [B, C, H, W] float32   flow: [B, H, W, 2] float32   out: [B, C, H, W]
// Bilinear warp, align_corners=True; identity grid folds into pixel index.
//
// Round-7 structure (scalar gathers, 2 px/thread at j-stride 32, 64x8 tile)
// + load batching: all 24 tap loads issued before any interpolation math,
// stores grouped last. Raises per-thread MLP 4 -> 24 to fill L1 queue bubbles.

#define B_   32
#define C_   3
#define H_   512
#define W_   512
#define LOGW 9
#define HW_  (H_ * W_)
#define TILE_W 64
#define TILE_H 8

__global__ __launch_bounds__(256)
void flow_warp_kernel(const float* __restrict__ x,
                      const float2* __restrict__ flow,
                      float* __restrict__ out)
{
    const unsigned tid  = threadIdx.x;
    const unsigned warp = tid >> 5;
    const unsigned lane = tid & 31u;

    const unsigned b  = blockIdx.z;
    const unsigned i  = blockIdx.y * TILE_H + warp;
    const unsigned j0 = blockIdx.x * TILE_W + lane;
    const unsigned j1 = j0 + 32;

    const unsigned hw0  = (i << LOGW) + j0;
    const unsigned hw1  = hw0 + 32;
    const unsigned bhw0 = (b << 18) + hw0;

    const float2 f0 = flow[bhw0];
    const float2 f1 = flow[bhw0 + 32];

    const float Hm1 = (float)(H_ - 1), Wm1 = (float)(W_ - 1);
    const float fi0 = (float)i  + Hm1 * 0.5f * f0.y;
    const float fj0 = (float)j0 + Wm1 * 0.5f * f0.x;
    const float fi1 = (float)i  + Hm1 * 0.5f * f1.y;
    const float fj1 = (float)j1 + Wm1 * 0.5f * f1.x;

    // pixel 0 taps
    const float i1f0 = fminf(fmaxf(floorf(fi0), 0.0f), Hm1);
    const float j1f0 = fminf(fmaxf(floorf(fj0), 0.0f), Wm1);
    const float i2f0 = fminf(i1f0 + 1.0f, Hm1);
    const float j2f0 = fminf(j1f0 + 1.0f, Wm1);
    const float di0 = fi0 - i1f0;
    const float dj0 = fj0 - j1f0;

    // pixel 1 taps
    const float i1f1 = fminf(fmaxf(floorf(fi1), 0.0f), Hm1);
    const float j1f1 = fminf(fmaxf(floorf(fj1), 0.0f), Wm1);
    const float i2f1 = fminf(i1f1 + 1.0f, Hm1);
    const float j2f1 = fminf(j1f1 + 1.0f, Wm1);
    const float di1 = fi1 - i1f1;
    const float dj1 = fj1 - j1f1;

    const unsigned o11_0 = ((unsigned)i1f0 << LOGW) + (unsigned)j1f0;
    const unsigned o12_0 = ((unsigned)i1f0 << LOGW) + (unsigned)j2f0;
    const unsigned o21_0 = ((unsigned)i2f0 << LOGW) + (unsigned)j1f0;
    const unsigned o22_0 = ((unsigned)i2f0 << LOGW) + (unsigned)j2f0;

    const unsigned o11_1 = ((unsigned)i1f1 << LOGW) + (unsigned)j1f1;
    const unsigned o12_1 = ((unsigned)i1f1 << LOGW) + (unsigned)j2f1;
    const unsigned o21_1 = ((unsigned)i2f1 << LOGW) + (unsigned)j1f1;
    const unsigned o22_1 = ((unsigned)i2f1 << LOGW) + (unsigned)j2f1;

    const unsigned base = b * (C_ * HW_);
    const float* xb = x + base;
    float* ob = out + base;

    // ---- batch ALL tap loads first (24 independent LDGs in flight) ----
    float t[C_][8];
    #pragma unroll
    for (int c = 0; c < C_; ++c) {
        const float* xc = xb + c * HW_;
        t[c][0] = __ldg(xc + o11_0);
        t[c][1] = __ldg(xc + o21_0);
        t[c][2] = __ldg(xc + o12_0);
        t[c][3] = __ldg(xc + o22_0);
        t[c][4] = __ldg(xc + o11_1);
        t[c][5] = __ldg(xc + o21_1);
        t[c][6] = __ldg(xc + o12_1);
        t[c][7] = __ldg(xc + o22_1);
    }

    // ---- weights ----
    const float w11_0 = (1.0f - di0) * (1.0f - dj0);
    const float w21_0 = di0 * (1.0f - dj0);
    const float w12_0 = (1.0f - di0) * dj0;
    const float w22_0 = di0 * dj0;

    const float w11_1 = (1.0f - di1) * (1.0f - dj1);
    const float w21_1 = di1 * (1.0f - dj1);
    const float w12_1 = (1.0f - di1) * dj1;
    const float w22_1 = di1 * dj1;

    // ---- interpolate + store ----
    #pragma unroll
    for (int c = 0; c < C_; ++c) {
        const float q0 = t[c][0] * w11_0 + t[c][1] * w21_0
                       + t[c][2] * w12_0 + t[c][3] * w22_0;
        const float q1 = t[c][4] * w11_1 + t[c][5] * w21_1
                       + t[c][6] * w12_1 + t[c][7] * w22_1;
        ob[c * HW_ + hw0] = q0;
        ob[c * HW_ + hw1] = q1;
    }
}

extern "C" void kernel_launch(void* const* d_in, const int* in_sizes, int n_in,
                              void* d_out, int out_size)
{
    const float*  x    = (const float*)d_in[0];
    const float2* flow = (const float2*)d_in[1];
    float* out = (float*)d_out;

    dim3 grid(W_ / TILE_W, H_ / TILE_H, B_);   // (8, 64, 32)
    flow_warp_kernel<<<grid, 256>>>(x, flow, out);
}